// round 5
// baseline (speedup 1.0000x reference)
#include <cuda_runtime.h>
#include <cuda_fp16.h>
#include <cstdint>

// Problem constants (fixed by the reference)
#define NN 50000
#define NE 600000
#define NG 64
#define D_IN 128
#define D_HID 128
#define D_OUT 64

// ---------------- device scratch (no allocs allowed) ----------------
__device__ __align__(16) int    g_cnt[NN];        // in-degree incl self loop
__device__ __align__(16) float  g_dinv[NN];
__device__ __align__(16) int    g_rowptr[NN + 1];
__device__ __align__(16) int    g_fillptr[NN];
__device__ __align__(16) int    g_bsum[256];
__device__ __align__(16) int    g_boff[256];
__device__ __align__(16) int    g_col[NE];
__device__ __align__(16) __half g_hs1[NN * D_HID];   // (x@W1)*dinv[row], fp16
__device__ __align__(16) float  g_out1[NN * D_HID];  // relu(layer1 agg), fp32
__device__ __align__(16) __half g_hs2[NN * D_OUT];   // (out1@W2)*dinv[row], fp16
__device__ __align__(16) float  g_gsum[NG * D_OUT];
__device__ __align__(16) int    g_gcnt[NG];

// ---------------- init ----------------
__global__ void k_init(int n) {
    int i = blockIdx.x * blockDim.x + threadIdx.x;
    if (i < n) g_cnt[i] = 1;                 // self loop
    if (i < NG * D_OUT) g_gsum[i] = 0.0f;
    if (i < NG) g_gcnt[i] = 0;
}

// ---------------- degree ----------------
__global__ void k_deg(const int* __restrict__ ei, int e) {
    int i = blockIdx.x * blockDim.x + threadIdx.x;
    if (i < e) {
        int d = ei[e + i];                   // dst row
        atomicAdd(&g_cnt[d], 1);
    }
}

// ---------------- CSR build: scan of (cnt-1) ----------------
__global__ void k_scan1(int n) {
    __shared__ int s[256];
    int t = threadIdx.x, b = blockIdx.x;
    int i = b * 256 + t;
    int v = (i < n) ? (g_cnt[i] - 1) : 0;
    s[t] = v;
    __syncthreads();
    #pragma unroll
    for (int off = 1; off < 256; off <<= 1) {
        int add = (t >= off) ? s[t - off] : 0;
        __syncthreads();
        s[t] += add;
        __syncthreads();
    }
    if (i < n) g_rowptr[i] = s[t] - v;       // block-local exclusive
    if (t == 255) g_bsum[b] = s[255];
}

__global__ void k_scan2(int nb) {
    __shared__ int s[256];
    int t = threadIdx.x;
    int v = (t < nb) ? g_bsum[t] : 0;
    s[t] = v;
    __syncthreads();
    #pragma unroll
    for (int off = 1; off < 256; off <<= 1) {
        int add = (t >= off) ? s[t - off] : 0;
        __syncthreads();
        s[t] += add;
        __syncthreads();
    }
    g_boff[t] = s[t] - v;                    // exclusive block offsets
}

// scan finalize + dinv (fused)
__global__ void k_scan3(int n, int e) {
    int i = blockIdx.x * blockDim.x + threadIdx.x;
    if (i < n) {
        int val = g_rowptr[i] + g_boff[i >> 8];
        g_rowptr[i] = val;
        g_fillptr[i] = val;
        g_dinv[i] = rsqrtf((float)g_cnt[i]);
    }
    if (i == 0) g_rowptr[n] = e;
}

__global__ void k_fill(const int* __restrict__ ei, int e) {
    int i = blockIdx.x * blockDim.x + threadIdx.x;
    if (i < e) {
        int s = ei[i];
        int d = ei[e + i];
        int pos = atomicAdd(&g_fillptr[d], 1);
        g_col[pos] = s;
    }
}

// ---------------- GEMM: out[r] = half( (X[r,:] @ W) * dinv[r] ) -------------
// X: [M,128] row-major fp32, W: [128,N] row-major fp32. Output fp16.
// LAYER=1: X=arg, out=g_hs1. LAYER=2: X=g_out1, out=g_hs2.
template <int N, int LAYER>
__global__ __launch_bounds__(256) void k_gemm(const float* __restrict__ Xarg,
                                              const float* __restrict__ W,
                                              int M) {
    constexpr int K  = 128;
    constexpr int KC = 32;           // k chunk
    constexpr int TM = 64;           // rows per block
    constexpr int CG = N / 4;        // col groups of 4 per thread row
    constexpr int TY = 256 / CG;     // thread rows
    constexpr int RPT = TM / TY;     // rows per thread
    constexpr int XP = KC + 4;       // padded X chunk row

    __shared__ float Ws[KC * N];
    __shared__ float Xs[TM * XP];

    const float* X = (LAYER == 1) ? Xarg : (const float*)g_out1;
    __half2*     out = (LAYER == 1) ? (__half2*)g_hs1 : (__half2*)g_hs2;

    int tid = threadIdx.x;
    int tx = tid % CG, ty = tid / CG;
    int row0 = blockIdx.x * TM;

    float acc[RPT][4] = {};
    float4* Ws4 = (float4*)Ws;

    for (int k0 = 0; k0 < K; k0 += KC) {
        #pragma unroll
        for (int i = tid; i < KC * N / 4; i += 256) {
            int r = i / (N / 4), c = i % (N / 4);
            Ws4[i] = ((const float4*)W)[(k0 + r) * (N / 4) + c];
        }
        #pragma unroll
        for (int i = tid; i < TM * KC / 4; i += 256) {
            int r = i / (KC / 4), c4 = i % (KC / 4);
            int gr = row0 + r;
            float4 v = (gr < M) ? ((const float4*)X)[gr * (K / 4) + (k0 / 4) + c4]
                                : make_float4(0.f, 0.f, 0.f, 0.f);
            *(float4*)&Xs[r * XP + c4 * 4] = v;
        }
        __syncthreads();

        #pragma unroll
        for (int kk = 0; kk < KC; kk += 4) {
            float4 a4[RPT];
            #pragma unroll
            for (int r = 0; r < RPT; r++)
                a4[r] = *(float4*)&Xs[(ty + r * TY) * XP + kk];
            #pragma unroll
            for (int k2 = 0; k2 < 4; k2++) {
                float4 b = Ws4[((kk + k2) * N) / 4 + tx];
                #pragma unroll
                for (int r = 0; r < RPT; r++) {
                    float a = (&a4[r].x)[k2];
                    acc[r][0] = fmaf(a, b.x, acc[r][0]);
                    acc[r][1] = fmaf(a, b.y, acc[r][1]);
                    acc[r][2] = fmaf(a, b.z, acc[r][2]);
                    acc[r][3] = fmaf(a, b.w, acc[r][3]);
                }
            }
        }
        __syncthreads();
    }

    #pragma unroll
    for (int r = 0; r < RPT; r++) {
        int gr = row0 + ty + r * TY;
        if (gr < M) {
            float dv = g_dinv[gr];
            __half2 h0 = __floats2half2_rn(acc[r][0] * dv, acc[r][1] * dv);
            __half2 h1 = __floats2half2_rn(acc[r][2] * dv, acc[r][3] * dv);
            out[gr * (N / 2) + tx * 2 + 0] = h0;
            out[gr * (N / 2) + tx * 2 + 1] = h1;
        }
    }
}

__device__ __forceinline__ void acc_h2(float2& a, __half2 h) {
    float2 f = __half22float2(h);
    a.x += f.x; a.y += f.y;
}

// ---------------- aggregation layer 1: warp per node (DIM=128, fp16 in) ----
// out1 = relu( dinv[i]*(hs1[i] + sum_nbr hs1[s]) + b1 )   (fp32 out)
__global__ __launch_bounds__(256) void k_agg1(const float* __restrict__ bias, int n) {
    const __half2* hs = (const __half2*)g_hs1;   // row = 64 half2
    int warp = (blockIdx.x * blockDim.x + threadIdx.x) >> 5;
    int lane = threadIdx.x & 31;
    if (warp >= n) return;
    int node = warp;

    const __half2* selfp = hs + (size_t)node * 64 + lane;
    float2 a0 = __half22float2(selfp[0]);
    float2 a1 = __half22float2(selfp[32]);

    int e = g_rowptr[node];
    int t = g_rowptr[node + 1];
    for (; e + 4 <= t; e += 4) {
        int c0 = g_col[e], c1 = g_col[e + 1], c2 = g_col[e + 2], c3 = g_col[e + 3];
        const __half2* p0 = hs + (size_t)c0 * 64 + lane;
        const __half2* p1 = hs + (size_t)c1 * 64 + lane;
        const __half2* p2 = hs + (size_t)c2 * 64 + lane;
        const __half2* p3 = hs + (size_t)c3 * 64 + lane;
        __half2 v00 = p0[0], v01 = p0[32];
        __half2 v10 = p1[0], v11 = p1[32];
        __half2 v20 = p2[0], v21 = p2[32];
        __half2 v30 = p3[0], v31 = p3[32];
        acc_h2(a0, v00); acc_h2(a1, v01);
        acc_h2(a0, v10); acc_h2(a1, v11);
        acc_h2(a0, v20); acc_h2(a1, v21);
        acc_h2(a0, v30); acc_h2(a1, v31);
    }
    for (; e < t; e++) {
        const __half2* p0 = hs + (size_t)g_col[e] * 64 + lane;
        acc_h2(a0, p0[0]); acc_h2(a1, p0[32]);
    }

    float dv = g_dinv[node];
    float2 bb0 = ((const float2*)bias)[lane];
    float2 bb1 = ((const float2*)bias)[lane + 32];
    float2 o0, o1;
    o0.x = fmaxf(fmaf(a0.x, dv, bb0.x), 0.0f);
    o0.y = fmaxf(fmaf(a0.y, dv, bb0.y), 0.0f);
    o1.x = fmaxf(fmaf(a1.x, dv, bb1.x), 0.0f);
    o1.y = fmaxf(fmaf(a1.y, dv, bb1.y), 0.0f);
    float2* op = (float2*)g_out1 + (size_t)node * 64 + lane;
    op[0]  = o0;
    op[32] = o1;
}

// ---------------- aggregation layer 2: warp per node (DIM=64, fp16 in) -----
// pool += dinv[i]*(hs2[i] + sum_nbr hs2[s]) + b2
__global__ __launch_bounds__(256) void k_agg2(const float* __restrict__ bias,
                                              const int* __restrict__ batch, int n) {
    const __half2* hs = (const __half2*)g_hs2;   // row = 32 half2
    int warp = (blockIdx.x * blockDim.x + threadIdx.x) >> 5;
    int lane = threadIdx.x & 31;
    if (warp >= n) return;
    int node = warp;

    float2 a0 = __half22float2(hs[(size_t)node * 32 + lane]);

    int e = g_rowptr[node];
    int t = g_rowptr[node + 1];
    for (; e + 4 <= t; e += 4) {
        int c0 = g_col[e], c1 = g_col[e + 1], c2 = g_col[e + 2], c3 = g_col[e + 3];
        __half2 v0 = hs[(size_t)c0 * 32 + lane];
        __half2 v1 = hs[(size_t)c1 * 32 + lane];
        __half2 v2 = hs[(size_t)c2 * 32 + lane];
        __half2 v3 = hs[(size_t)c3 * 32 + lane];
        acc_h2(a0, v0); acc_h2(a0, v1); acc_h2(a0, v2); acc_h2(a0, v3);
    }
    for (; e < t; e++)
        acc_h2(a0, hs[(size_t)g_col[e] * 32 + lane]);

    float dv = g_dinv[node];
    float2 bb = ((const float2*)bias)[lane];
    float vx = fmaf(a0.x, dv, bb.x);
    float vy = fmaf(a0.y, dv, bb.y);
    int gidx = batch[node];
    atomicAdd(&g_gsum[gidx * D_OUT + 2 * lane + 0], vx);
    atomicAdd(&g_gsum[gidx * D_OUT + 2 * lane + 1], vy);
}

// ---------------- graph counts ----------------
__global__ void k_count(const int* __restrict__ batch, int n) {
    __shared__ int hist[NG];
    int t = threadIdx.x;
    if (t < NG) hist[t] = 0;
    __syncthreads();
    int i = blockIdx.x * blockDim.x + t;
    if (i < n) atomicAdd(&hist[batch[i]], 1);
    __syncthreads();
    if (t < NG && hist[t]) atomicAdd(&g_gcnt[t], hist[t]);
}

// ---------------- final divide ----------------
__global__ void k_final(float* __restrict__ out) {
    int i = blockIdx.x * blockDim.x + threadIdx.x;
    if (i < NG * D_OUT) {
        int g = i / D_OUT;
        float c = (float)max(g_gcnt[g], 1);
        out[i] = g_gsum[i] / c;
    }
}

// ---------------- launch (NO host runtime API calls — graph-capturable) ----
extern "C" void kernel_launch(void* const* d_in, const int* in_sizes, int n_in,
                              void* d_out, int out_size) {
    // Identify inputs by element count (all distinct) — robust to ordering.
    const float* x = nullptr; const int* ei = nullptr; const int* batch = nullptr;
    const float* W1 = nullptr; const float* b1 = nullptr;
    const float* W2 = nullptr; const float* b2 = nullptr;
    for (int i = 0; i < n_in; i++) {
        switch (in_sizes[i]) {
            case NN * D_IN:      x     = (const float*)d_in[i]; break;  // 6,400,000
            case 2 * NE:         ei    = (const int*)d_in[i];   break;  // 1,200,000
            case NN:             batch = (const int*)d_in[i];   break;  // 50,000
            case D_IN * D_HID:   W1    = (const float*)d_in[i]; break;  // 16,384
            case D_HID * D_OUT:  W2    = (const float*)d_in[i]; break;  // 8,192
            case D_HID:          b1    = (const float*)d_in[i]; break;  // 128
            case D_OUT:          b2    = (const float*)d_in[i]; break;  // 64
        }
    }
    float* out = (float*)d_out;               // [64,64]

    const int n = NN, e = NE;
    const int nb256n = (n + 255) / 256;   // 196
    const int nb256e = (e + 255) / 256;

    k_init<<<nb256n, 256>>>(n);
    k_deg<<<nb256e, 256>>>(ei, e);
    k_scan1<<<nb256n, 256>>>(n);
    k_scan2<<<1, 256>>>(nb256n);
    k_scan3<<<nb256n, 256>>>(n, e);
    k_fill<<<nb256e, 256>>>(ei, e);

    int gb = (n + 63) / 64;               // 782 GEMM blocks
    k_gemm<128, 1><<<gb, 256>>>(x, W1, n);
    k_agg1<<<(n + 7) / 8, 256>>>(b1, n);
    k_gemm<64, 2><<<gb, 256>>>(nullptr, W2, n);
    k_agg2<<<(n + 7) / 8, 256>>>(b2, batch, n);
    k_count<<<nb256n, 256>>>(batch, n);
    k_final<<<(NG * D_OUT + 255) / 256, 256>>>(out);
}

// round 6
// speedup vs baseline: 1.3819x; 1.3819x over previous
#include <cuda_runtime.h>
#include <cuda_fp16.h>
#include <cstdint>

// Problem constants (fixed by the reference)
#define NN 50000
#define NE 600000
#define NG 64
#define D_IN 128
#define D_HID 128
#define D_OUT 64

// ---------------- device scratch (no allocs allowed) ----------------
// Invariant: g_cnt, g_gsum, g_gcnt are ZERO at entry of every kernel_launch
// call (BSS-zero initially; each run re-zeroes them at the end of k_fill /
// k_final). This keeps the launch graph deterministic across replays.
__device__ __align__(16) int    g_cnt[NN];        // in-degree (edges only)
__device__ __align__(16) float  g_dinv[NN];
__device__ __align__(16) int    g_rowptr[NN + 1];
__device__ __align__(16) int    g_fillptr[NN];
__device__ __align__(16) int    g_bsum[256];
__device__ __align__(16) int    g_boff[256];
__device__ __align__(16) int    g_col[NE];
__device__ __align__(16) __half g_hs1[NN * D_HID];   // (x@W1)*dinv[row], fp16
__device__ __align__(16) __half g_out1[NN * D_HID];  // relu(layer1 agg), fp16
__device__ __align__(16) __half g_hs2[NN * D_OUT];   // (out1@W2)*dinv[row], fp16
__device__ __align__(16) float  g_gsum[NG * D_OUT];
__device__ __align__(16) int    g_gcnt[NG];

// ---------------- degree + graph-size histogram (fused) ----------------
__global__ void k_deg(const int* __restrict__ ei, const int* __restrict__ batch,
                      int e, int n) {
    __shared__ int hist[NG];
    int t = threadIdx.x;
    if (t < NG) hist[t] = 0;
    __syncthreads();
    int i = blockIdx.x * blockDim.x + t;
    if (i < e) atomicAdd(&g_cnt[ei[e + i]], 1);
    if (i < n) atomicAdd(&hist[batch[i]], 1);
    __syncthreads();
    if (t < NG && hist[t]) atomicAdd(&g_gcnt[t], hist[t]);
}

// ---------------- CSR build: scan of cnt ----------------
__global__ void k_scan1(int n) {
    __shared__ int s[256];
    int t = threadIdx.x, b = blockIdx.x;
    int i = b * 256 + t;
    int v = (i < n) ? g_cnt[i] : 0;
    s[t] = v;
    __syncthreads();
    #pragma unroll
    for (int off = 1; off < 256; off <<= 1) {
        int add = (t >= off) ? s[t - off] : 0;
        __syncthreads();
        s[t] += add;
        __syncthreads();
    }
    if (i < n) g_rowptr[i] = s[t] - v;       // block-local exclusive
    if (t == 255) g_bsum[b] = s[255];
}

__global__ void k_scan2(int nb) {
    __shared__ int s[256];
    int t = threadIdx.x;
    int v = (t < nb) ? g_bsum[t] : 0;
    s[t] = v;
    __syncthreads();
    #pragma unroll
    for (int off = 1; off < 256; off <<= 1) {
        int add = (t >= off) ? s[t - off] : 0;
        __syncthreads();
        s[t] += add;
        __syncthreads();
    }
    g_boff[t] = s[t] - v;                    // exclusive block offsets
}

// scan finalize + dinv (self-loop folded: deg = cnt + 1)
__global__ void k_scan3(int n, int e) {
    int i = blockIdx.x * blockDim.x + threadIdx.x;
    if (i < n) {
        int val = g_rowptr[i] + g_boff[i >> 8];
        g_rowptr[i] = val;
        g_fillptr[i] = val;
        g_dinv[i] = rsqrtf((float)(g_cnt[i] + 1));
    }
    if (i == 0) g_rowptr[n] = e;
}

// fill CSR cols; re-zero g_cnt for the next replay
__global__ void k_fill(const int* __restrict__ ei, int e, int n) {
    int i = blockIdx.x * blockDim.x + threadIdx.x;
    if (i < e) {
        int s = ei[i];
        int d = ei[e + i];
        int pos = atomicAdd(&g_fillptr[d], 1);
        g_col[pos] = s;
    }
    if (i < n) g_cnt[i] = 0;
}

// ---------------- tensor-core GEMM ----------------
// out[r,:] = half( (X[r,:128] @ W[:128,:N]) * dinv[r] )
// LAYER=1: X = fp32 arg -> g_hs1.  LAYER=2: X = g_out1 (fp16) -> g_hs2.
// BM=64 rows/block, 256 threads = 8 warps (4 row-groups x 2 col-groups).
// Smem fp16, 16B-unit XOR swizzle for conflict-free ldmatrix.

__device__ __forceinline__ uint32_t smem_u32(const void* p) {
    return (uint32_t)__cvta_generic_to_shared(p);
}
__device__ __forceinline__ void ldsm_x4(uint32_t& a0, uint32_t& a1,
                                        uint32_t& a2, uint32_t& a3, uint32_t addr) {
    asm volatile("ldmatrix.sync.aligned.m8n8.x4.shared.b16 {%0,%1,%2,%3},[%4];"
                 : "=r"(a0), "=r"(a1), "=r"(a2), "=r"(a3) : "r"(addr));
}
__device__ __forceinline__ void ldsm_x2t(uint32_t& b0, uint32_t& b1, uint32_t addr) {
    asm volatile("ldmatrix.sync.aligned.m8n8.x2.trans.shared.b16 {%0,%1},[%2];"
                 : "=r"(b0), "=r"(b1) : "r"(addr));
}
__device__ __forceinline__ void mma16816(float* c, uint32_t a0, uint32_t a1,
                                         uint32_t a2, uint32_t a3,
                                         uint32_t b0, uint32_t b1) {
    asm volatile(
        "mma.sync.aligned.m16n8k16.row.col.f32.f16.f16.f32 "
        "{%0,%1,%2,%3}, {%4,%5,%6,%7}, {%8,%9}, {%0,%1,%2,%3};"
        : "+f"(c[0]), "+f"(c[1]), "+f"(c[2]), "+f"(c[3])
        : "r"(a0), "r"(a1), "r"(a2), "r"(a3), "r"(b0), "r"(b1));
}
__device__ __forceinline__ uint4 f8_to_h8(float4 f0, float4 f1) {
    __half2 p0 = __floats2half2_rn(f0.x, f0.y), p1 = __floats2half2_rn(f0.z, f0.w);
    __half2 p2 = __floats2half2_rn(f1.x, f1.y), p3 = __floats2half2_rn(f1.z, f1.w);
    uint4 v;
    v.x = *(uint32_t*)&p0; v.y = *(uint32_t*)&p1;
    v.z = *(uint32_t*)&p2; v.w = *(uint32_t*)&p3;
    return v;
}

template <int N, int LAYER>
__global__ __launch_bounds__(256) void k_mma(const float* __restrict__ Xf,
                                             const float* __restrict__ W, int M) {
    constexpr int K  = 128;
    constexpr int UW = N / 8;            // 16B units per W row
    constexpr int NT = N / 16;           // n-tiles (8 cols) per warp
    __shared__ __align__(16) __half Xs[64 * K];   // 16KB
    __shared__ __align__(16) __half Ws[K * N];    // 32KB (N=128) / 16KB

    int tid = threadIdx.x;
    int row0 = blockIdx.x * 64;

    // ---- load W (fp32 -> fp16, swizzled) ----
    #pragma unroll
    for (int t = tid; t < K * UW; t += 256) {
        int r = t / UW, u = t % UW;
        const float4* src = (const float4*)(W + r * N + u * 8);
        uint4 v = f8_to_h8(src[0], src[1]);
        *(uint4*)(Xs + 0, Ws + ((r * UW) + (u ^ (r & 7))) * 8) = v;
    }
    // ---- load X tile (swizzled) ----
    if (LAYER == 1) {
        #pragma unroll
        for (int t = tid; t < 64 * 16; t += 256) {
            int r = t / 16, u = t % 16;
            int gr = min(row0 + r, M - 1);
            const float4* src = (const float4*)(Xf + (size_t)gr * K + u * 8);
            uint4 v = f8_to_h8(src[0], src[1]);
            *(uint4*)(Ws + 0, Xs + ((r * 16) + (u ^ (r & 7))) * 8) = v;
        }
    } else {
        const uint4* Xh = (const uint4*)g_out1;  // 16 units per 128-half row
        #pragma unroll
        for (int t = tid; t < 64 * 16; t += 256) {
            int r = t / 16, u = t % 16;
            int gr = min(row0 + r, M - 1);
            uint4 v = Xh[(size_t)gr * 16 + u];
            *(uint4*)(Ws + 0, Xs + ((r * 16) + (u ^ (r & 7))) * 8) = v;
        }
    }
    __syncthreads();

    int lane = tid & 31, wid = tid >> 5;
    int wm = wid >> 1, wn = wid & 1;

    float acc[NT][4];
    #pragma unroll
    for (int j = 0; j < NT; j++)
        #pragma unroll
        for (int q = 0; q < 4; q++) acc[j][q] = 0.0f;

    int ar = wm * 16 + (lane & 15);
    int asel = lane >> 4;
    int brr = lane & 15;

    #pragma unroll
    for (int ks = 0; ks < 8; ks++) {
        uint32_t a0, a1, a2, a3;
        int uA = ks * 2 + asel;
        ldsm_x4(a0, a1, a2, a3,
                smem_u32(&Xs[((ar * 16) + (uA ^ (ar & 7))) * 8]));
        int rB = ks * 16 + brr;
        #pragma unroll
        for (int j = 0; j < NT; j++) {
            int uB = (wn * (N / 2) + j * 8) >> 3;
            uint32_t b0, b1;
            ldsm_x2t(b0, b1, smem_u32(&Ws[((rB * UW) + (uB ^ (rB & 7))) * 8]));
            mma16816(acc[j], a0, a1, a2, a3, b0, b1);
        }
    }

    // ---- epilogue: *dinv, fp16 store ----
    int r0l = wm * 16 + (lane >> 2);
    int gr0 = row0 + r0l, gr1 = gr0 + 8;
    float dv0 = (gr0 < M) ? g_dinv[gr0] : 0.0f;
    float dv1 = (gr1 < M) ? g_dinv[gr1] : 0.0f;
    __half2* out = (LAYER == 1) ? (__half2*)g_hs1 : (__half2*)g_hs2;
    #pragma unroll
    for (int j = 0; j < NT; j++) {
        int c2 = wn * (N / 4) + j * 4 + (lane & 3);   // half2 index in row
        if (gr0 < M)
            out[(size_t)gr0 * (N / 2) + c2] =
                __floats2half2_rn(acc[j][0] * dv0, acc[j][1] * dv0);
        if (gr1 < M)
            out[(size_t)gr1 * (N / 2) + c2] =
                __floats2half2_rn(acc[j][2] * dv1, acc[j][3] * dv1);
    }
}

__device__ __forceinline__ void acc_h2(float2& a, __half2 h) {
    float2 f = __half22float2(h);
    a.x += f.x; a.y += f.y;
}

// ---------------- aggregation layer 1 (DIM=128, fp16 in, fp16 out) ----
__global__ __launch_bounds__(256) void k_agg1(const float* __restrict__ bias, int n) {
    const __half2* hs = (const __half2*)g_hs1;   // row = 64 half2
    int warp = (blockIdx.x * blockDim.x + threadIdx.x) >> 5;
    int lane = threadIdx.x & 31;
    if (warp >= n) return;
    int node = warp;

    const __half2* selfp = hs + (size_t)node * 64 + lane;
    float2 a0 = __half22float2(selfp[0]);
    float2 a1 = __half22float2(selfp[32]);

    int e = g_rowptr[node];
    int t = g_rowptr[node + 1];
    for (; e + 4 <= t; e += 4) {
        int c0 = g_col[e], c1 = g_col[e + 1], c2 = g_col[e + 2], c3 = g_col[e + 3];
        const __half2* p0 = hs + (size_t)c0 * 64 + lane;
        const __half2* p1 = hs + (size_t)c1 * 64 + lane;
        const __half2* p2 = hs + (size_t)c2 * 64 + lane;
        const __half2* p3 = hs + (size_t)c3 * 64 + lane;
        __half2 v00 = p0[0], v01 = p0[32];
        __half2 v10 = p1[0], v11 = p1[32];
        __half2 v20 = p2[0], v21 = p2[32];
        __half2 v30 = p3[0], v31 = p3[32];
        acc_h2(a0, v00); acc_h2(a1, v01);
        acc_h2(a0, v10); acc_h2(a1, v11);
        acc_h2(a0, v20); acc_h2(a1, v21);
        acc_h2(a0, v30); acc_h2(a1, v31);
    }
    for (; e < t; e++) {
        const __half2* p0 = hs + (size_t)g_col[e] * 64 + lane;
        acc_h2(a0, p0[0]); acc_h2(a1, p0[32]);
    }

    float dv = g_dinv[node];
    float2 bb0 = ((const float2*)bias)[lane];
    float2 bb1 = ((const float2*)bias)[lane + 32];
    __half2* op = (__half2*)g_out1 + (size_t)node * 64 + lane;
    op[0]  = __floats2half2_rn(fmaxf(fmaf(a0.x, dv, bb0.x), 0.0f),
                               fmaxf(fmaf(a0.y, dv, bb0.y), 0.0f));
    op[32] = __floats2half2_rn(fmaxf(fmaf(a1.x, dv, bb1.x), 0.0f),
                               fmaxf(fmaf(a1.y, dv, bb1.y), 0.0f));
}

// ---------------- aggregation layer 2 (DIM=64, fp16 in, pool) ----------
__global__ __launch_bounds__(256) void k_agg2(const float* __restrict__ bias,
                                              const int* __restrict__ batch, int n) {
    const __half2* hs = (const __half2*)g_hs2;   // row = 32 half2
    int warp = (blockIdx.x * blockDim.x + threadIdx.x) >> 5;
    int lane = threadIdx.x & 31;
    if (warp >= n) return;
    int node = warp;

    float2 a0 = __half22float2(hs[(size_t)node * 32 + lane]);

    int e = g_rowptr[node];
    int t = g_rowptr[node + 1];
    for (; e + 4 <= t; e += 4) {
        int c0 = g_col[e], c1 = g_col[e + 1], c2 = g_col[e + 2], c3 = g_col[e + 3];
        __half2 v0 = hs[(size_t)c0 * 32 + lane];
        __half2 v1 = hs[(size_t)c1 * 32 + lane];
        __half2 v2 = hs[(size_t)c2 * 32 + lane];
        __half2 v3 = hs[(size_t)c3 * 32 + lane];
        acc_h2(a0, v0); acc_h2(a0, v1); acc_h2(a0, v2); acc_h2(a0, v3);
    }
    for (; e < t; e++)
        acc_h2(a0, hs[(size_t)g_col[e] * 32 + lane]);

    float dv = g_dinv[node];
    float2 bb = ((const float2*)bias)[lane];
    int gidx = batch[node];
    atomicAdd(&g_gsum[gidx * D_OUT + 2 * lane + 0], fmaf(a0.x, dv, bb.x));
    atomicAdd(&g_gsum[gidx * D_OUT + 2 * lane + 1], fmaf(a0.y, dv, bb.y));
}

// ---------------- final divide + re-zero pool state ----------------
__global__ void k_final(float* __restrict__ out) {
    int i = blockIdx.x * blockDim.x + threadIdx.x;
    if (i < NG * D_OUT) {
        int g = i / D_OUT;
        float c = (float)max(g_gcnt[g], 1);
        out[i] = g_gsum[i] / c;
        g_gsum[i] = 0.0f;
    }
    if (i < NG) g_gcnt[i] = 0;
}

// ---------------- launch (graph-capturable; no host API calls) ----------
extern "C" void kernel_launch(void* const* d_in, const int* in_sizes, int n_in,
                              void* d_out, int out_size) {
    const float* x = nullptr; const int* ei = nullptr; const int* batch = nullptr;
    const float* W1 = nullptr; const float* b1 = nullptr;
    const float* W2 = nullptr; const float* b2 = nullptr;
    for (int i = 0; i < n_in; i++) {
        switch (in_sizes[i]) {
            case NN * D_IN:      x     = (const float*)d_in[i]; break;
            case 2 * NE:         ei    = (const int*)d_in[i];   break;
            case NN:             batch = (const int*)d_in[i];   break;
            case D_IN * D_HID:   W1    = (const float*)d_in[i]; break;
            case D_HID * D_OUT:  W2    = (const float*)d_in[i]; break;
            case D_HID:          b1    = (const float*)d_in[i]; break;
            case D_OUT:          b2    = (const float*)d_in[i]; break;
        }
    }
    float* out = (float*)d_out;

    const int n = NN, e = NE;
    const int nb256n = (n + 255) / 256;   // 196
    const int nb256e = (e + 255) / 256;

    k_deg<<<nb256e, 256>>>(ei, batch, e, n);
    k_scan1<<<nb256n, 256>>>(n);
    k_scan2<<<1, 256>>>(nb256n);
    k_scan3<<<nb256n, 256>>>(n, e);
    k_fill<<<nb256e, 256>>>(ei, e, n);

    int gb = (n + 63) / 64;               // 782
    k_mma<128, 1><<<gb, 256>>>(x, W1, n);
    k_agg1<<<(n + 7) / 8, 256>>>(b1, n);
    k_mma<64, 2><<<gb, 256>>>(nullptr, W2, n);
    k_agg2<<<(n + 7) / 8, 256>>>(b2, batch, n);
    k_final<<<(NG * D_OUT + 255) / 256, 256>>>(out);
}